// round 1
// baseline (speedup 1.0000x reference)
#include <cuda_runtime.h>

// YOLOv3 loss, sparsity-exploiting implementation.
// Scales: s=0 -> 13x13 (anchors 6,7,8), s=1 -> 26x26 (3,4,5), s=2 -> 52x52 (0,1,2)
// pred layout: [B, A*(5+C), H, W]; channel c of anchor a at plane a*85+c.

#define B_SZ 32
#define N_TGT 20
#define NUM_CLASSES 80
#define IGNORE_THRESH 0.5f
#define IMG_SIZE 416.0f

// cell index = CELLBASE[s] + ((b*3+a)*HW + gj*W + gi)
// scale cell counts: 96*169=16224, 96*676=64896, 96*2704=259584 ; total 340704
#define CELLS_TOTAL 340704
#define NWORDS 10647            // ceil(340704/32)
#define MAX_ENTRIES (96 * N_TGT)

__device__ unsigned int g_bits[NWORDS];          // pos | ignore exclusion bitmap
__device__ int          g_counts[96];            // entries per (b,scale)
__device__ int          g_key[MAX_ENTRIES];      // (a<<16)|(gj<<8)|gi
__device__ float        g_tx[MAX_ENTRIES], g_ty[MAX_ENTRIES];
__device__ float        g_tw[MAX_ENTRIES], g_th[MAX_ENTRIES];
__device__ unsigned int g_cls[MAX_ENTRIES][3];   // 80-bit class multi-hot
__device__ double       g_acc_pos;
__device__ double       g_acc_noobj;
__device__ int          g_numpos;

__device__ __forceinline__ float sp(float x) {
    // jax.nn.softplus: logaddexp(x, 0) = max(x,0) + log1p(exp(-|x|))
    return fmaxf(x, 0.0f) + log1pf(expf(-fabsf(x)));
}
__device__ __forceinline__ float bce(float x, float t) {
    return sp(x) - x * t;
}

// ---------------------------------------------------------------------------
// Kernel 1: zero scratch + build targets (1 block, 128 threads; 96 active builders)
// ---------------------------------------------------------------------------
__global__ __launch_bounds__(128, 1)
void k_build(const float* __restrict__ targets,
             const unsigned int* __restrict__ valid,   // [B,N] nonzero = valid
             const float* __restrict__ anchors)        // [9,2]
{
    const int tid = threadIdx.x;

    for (int i = tid; i < NWORDS; i += 128) g_bits[i] = 0u;
    for (int i = tid; i < 96; i += 128) g_counts[i] = 0;
    if (tid == 0) { g_acc_pos = 0.0; g_acc_noobj = 0.0; g_numpos = 0; }
    __syncthreads();

    if (tid >= 96) return;
    const int b = tid / 3;
    const int s = tid % 3;

    const int Wd  = (s == 0) ? 13 : (s == 1) ? 26 : 52;
    const int HW  = Wd * Wd;
    const int cellbase = (s == 0) ? 0 : (s == 1) ? 16224 : 81120;

    // anchor mask: s=0 -> {6,7,8}, s=1 -> {3,4,5}, s=2 -> {0,1,2}
    const int abase = (2 - s) * 3;
    float aw[3], ah[3];
    #pragma unroll
    for (int a = 0; a < 3; a++) {
        aw[a] = anchors[(abase + a) * 2 + 0] / IMG_SIZE;
        ah[a] = anchors[(abase + a) * 2 + 1] / IMG_SIZE;
    }

    int          key[N_TGT];
    float        ltx[N_TGT], lty[N_TGT], ltw[N_TGT], lth[N_TGT];
    unsigned int lcls[N_TGT][3];
    int cnt = 0;

    for (int n = 0; n < N_TGT; n++) {
        if (valid[b * N_TGT + n] == 0u) continue;
        const float* t = targets + (size_t)(b * N_TGT + n) * 5;
        const float gx = t[0], gy = t[1], gw = t[2], gh = t[3];
        const int gc = (int)t[4];

        const float gxW = gx * (float)Wd;
        const float gyH = gy * (float)Wd;
        const int gi = min((int)gxW, Wd - 1);
        const int gj = min((int)gyH, Wd - 1);

        float best_iou = -1.0f; int best = 0;
        #pragma unroll
        for (int a = 0; a < 3; a++) {
            const float inter = fminf(gw, aw[a]) * fminf(gh, ah[a]);
            const float uni = gw * gh + aw[a] * ah[a] - inter + 1e-16f;
            const float iou = inter / uni;
            if (iou > IGNORE_THRESH) {
                const int cell = cellbase + ((b * 3 + a) * HW + gj * Wd + gi);
                atomicOr(&g_bits[cell >> 5], 1u << (cell & 31));
            }
            if (iou > best_iou) { best_iou = iou; best = a; }
        }

        const float vtx = gxW - (float)gi;
        const float vty = gyH - (float)gj;
        const float vtw = logf(gw / aw[best]);
        const float vth = logf(gh / ah[best]);

        // last-write-wins dedup on (a, gj, gi); class bits union (JAX .set scatter)
        const int k = (best << 16) | (gj << 8) | gi;
        int j;
        for (j = 0; j < cnt; j++) if (key[j] == k) break;
        if (j == cnt) {
            key[cnt] = k;
            lcls[cnt][0] = lcls[cnt][1] = lcls[cnt][2] = 0u;
            cnt++;
        }
        ltx[j] = vtx; lty[j] = vty; ltw[j] = vtw; lth[j] = vth;
        lcls[j][gc >> 5] |= 1u << (gc & 31);
    }

    for (int j = 0; j < cnt; j++) {
        const int a  = key[j] >> 16;
        const int gj = (key[j] >> 8) & 255;
        const int gi = key[j] & 255;
        const int cell = cellbase + ((b * 3 + a) * HW + gj * Wd + gi);
        atomicOr(&g_bits[cell >> 5], 1u << (cell & 31));   // pos -> excluded from noobj
        const int slot = tid * N_TGT + j;
        g_key[slot] = key[j];
        g_tx[slot] = ltx[j]; g_ty[slot] = lty[j];
        g_tw[slot] = ltw[j]; g_th[slot] = lth[j];
        g_cls[slot][0] = lcls[j][0]; g_cls[slot][1] = lcls[j][1]; g_cls[slot][2] = lcls[j][2];
    }
    g_counts[tid] = cnt;
    if (cnt > 0) atomicAdd(&g_numpos, cnt);
}

// ---------------------------------------------------------------------------
// Kernel 2: sparse positive-cell losses. 96 blocks (one per (b,scale)), 8 warps;
// one warp per entry, 85 channels across lanes.
// ---------------------------------------------------------------------------
__global__ __launch_bounds__(256, 1)
void k_sparse(const float* __restrict__ p0,
              const float* __restrict__ p1,
              const float* __restrict__ p2)
{
    const int bid = blockIdx.x;       // b*3+s
    const int cnt = g_counts[bid];
    const int warp = threadIdx.x >> 5;
    const int lane = threadIdx.x & 31;

    const int b = bid / 3;
    const int s = bid % 3;
    const int Wd = (s == 0) ? 13 : (s == 1) ? 26 : 52;
    const int HW = Wd * Wd;
    const float* __restrict__ p = (s == 0) ? p0 : (s == 1) ? p1 : p2;

    double local = 0.0;
    for (int j = warp; j < cnt; j += 8) {
        const int slot = bid * N_TGT + j;
        const int k  = g_key[slot];
        const int a  = k >> 16;
        const int gj = (k >> 8) & 255;
        const int gi = k & 255;
        const float tx = g_tx[slot], ty = g_ty[slot];
        const float tw = g_tw[slot], th = g_th[slot];
        const unsigned int m0 = g_cls[slot][0], m1 = g_cls[slot][1], m2 = g_cls[slot][2];

        const float* base = p + ((size_t)(b * 255 + a * 85)) * HW + (size_t)gj * Wd + gi;

        float sum = 0.0f;
        for (int c = lane; c < 85; c += 32) {
            const float x = base[(size_t)c * HW];
            float v;
            if (c == 0)      v = 5.0f * bce(x, tx);
            else if (c == 1) v = 5.0f * bce(x, ty);
            else if (c == 2) { const float d = x - tw; v = 5.0f * d * d; }
            else if (c == 3) { const float d = x - th; v = 5.0f * d * d; }
            else if (c == 4) v = sp(-x);
            else {
                const int cc = c - 5;
                const unsigned int mw = (cc < 32) ? m0 : (cc < 64) ? m1 : m2;
                const float t = ((mw >> (cc & 31)) & 1u) ? 1.0f : 0.0f;
                v = sp(x) - x * t;
            }
            sum += v;
        }
        #pragma unroll
        for (int off = 16; off; off >>= 1)
            sum += __shfl_down_sync(0xffffffffu, sum, off);
        if (lane == 0) local += (double)sum;
    }

    __shared__ double wsum[8];
    if (lane == 0) wsum[warp] = local;
    __syncthreads();
    if (threadIdx.x == 0) {
        double tot = 0.0;
        #pragma unroll
        for (int w = 0; w < 8; w++) tot += wsum[w];
        if (tot != 0.0) atomicAdd(&g_acc_pos, tot);
    }
}

// ---------------------------------------------------------------------------
// Kernel 3 (x3 scales): dense noobj sum over conf channel, skipping excluded cells.
// ---------------------------------------------------------------------------
template <int HW, int CELLBASE, int NCELLS>
__global__ __launch_bounds__(256, 8)
void k_noobj(const float* __restrict__ p)
{
    const int i = blockIdx.x * 256 + threadIdx.x;
    float v = 0.0f;
    if (i < NCELLS) {
        const int cell = CELLBASE + i;
        if (!((g_bits[cell >> 5] >> (cell & 31)) & 1u)) {
            const int plane = i / HW;           // b*3 + a
            const int pix   = i - plane * HW;
            const int b = plane / 3;
            const int a = plane - b * 3;
            v = sp(p[((size_t)(b * 255 + a * 85 + 4)) * HW + pix]);
        }
    }
    #pragma unroll
    for (int off = 16; off; off >>= 1)
        v += __shfl_down_sync(0xffffffffu, v, off);
    __shared__ float wsum[8];
    if ((threadIdx.x & 31) == 0) wsum[threadIdx.x >> 5] = v;
    __syncthreads();
    if (threadIdx.x == 0) {
        float tot = 0.0f;
        #pragma unroll
        for (int w = 0; w < 8; w++) tot += wsum[w];
        atomicAdd(&g_acc_noobj, (double)tot);
    }
}

// ---------------------------------------------------------------------------
// Kernel 4: finalize
// ---------------------------------------------------------------------------
__global__ void k_final(float* __restrict__ out)
{
    const double tot = g_acc_pos + 0.5 * g_acc_noobj;   // LAMBDA_NOOBJ = 0.5
    const int np = g_numpos;
    out[0] = (float)((np > 0) ? tot / (double)np : tot / (double)B_SZ);
}

// ---------------------------------------------------------------------------
extern "C" void kernel_launch(void* const* d_in, const int* in_sizes, int n_in,
                              void* d_out, int out_size)
{
    const float* p0      = (const float*)d_in[0];
    const float* p1      = (const float*)d_in[1];
    const float* p2      = (const float*)d_in[2];
    const float* targets = (const float*)d_in[3];
    const unsigned int* valid = (const unsigned int*)d_in[4];  // bool as 4-byte words
    const float* anchors = (const float*)d_in[5];

    k_build<<<1, 128>>>(targets, valid, anchors);
    k_sparse<<<96, 256>>>(p0, p1, p2);
    k_noobj<169,     0,  16224><<<(16224  + 255) / 256, 256>>>(p0);
    k_noobj<676, 16224,  64896><<<(64896  + 255) / 256, 256>>>(p1);
    k_noobj<2704,81120, 259584><<<(259584 + 255) / 256, 256>>>(p2);
    k_final<<<1, 1>>>((float*)d_out);
}

// round 5
// speedup vs baseline: 1.1356x; 1.1356x over previous
#include <cuda_runtime.h>

// YOLOv3 loss — single fused kernel.
// Identity: sum_{noobj} sp(conf) = sum_{ALL cells} sp(conf) - sum_{excluded} sp(conf).
// Excluded set (pos ∪ ignore) is local to one (b,scale) pair -> block-local target build.
// Device-global accumulators are reset by the finalizing block => graph-replay safe.
// conf-plane base: b*255 + a*85 + 4 == plane*85 + 4 with plane = 3b + a  (no div/mod by 3).

#define NUM_CLASSES 80
#define N_TGT 20
#define B_SZ 32
#define GRID 592
#define BLOCK 256
#define TTOT (GRID * BLOCK)

__device__ double       g_total  = 0.0;
__device__ int          g_numpos = 0;
__device__ unsigned int g_done   = 0u;

// fast softplus: max(x,0) + log(1 + exp(-|x|)) via raw MUFU ex2/lg2.
// abs err per term < 1.2e-7 (vs 1e-3 rel gate on an O(1e5) result) -- safe.
__device__ __forceinline__ float sp(float x) {
    const float t = __expf(-fabsf(x));
    return fmaxf(x, 0.0f) + __logf(1.0f + t);
}

// vectorized dense conf-channel softplus sum (HW divisible by 4)
template <int HW>
__device__ __forceinline__ float dense_sum4(const float* __restrict__ p, int gtid) {
    constexpr int Q = HW / 4;
    float s = 0.0f;
    for (int i = gtid; i < 96 * Q; i += TTOT) {
        const int plane = i / Q;            // plane = b*3 + a
        const int q     = i - plane * Q;
        const float4 v = *(const float4*)(p + (size_t)(plane * 85 + 4) * HW + 4 * q);
        s += sp(v.x) + sp(v.y) + sp(v.z) + sp(v.w);
    }
    return s;
}

__global__ __launch_bounds__(BLOCK)
void k_main(const float* __restrict__ p0,
            const float* __restrict__ p1,
            const float* __restrict__ p2,
            const float* __restrict__ targets,
            const unsigned int* __restrict__ valid,   // [B,N] nonzero = valid
            const float* __restrict__ anchors,        // [9,2]
            float* __restrict__ out)
{
    const int tid  = threadIdx.x;
    const int bid  = blockIdx.x;
    const int gtid = bid * BLOCK + tid;

    __shared__ int          s_key[N_TGT];
    __shared__ float        s_tx[N_TGT], s_ty[N_TGT], s_tw[N_TGT], s_th[N_TGT];
    __shared__ unsigned int s_cls[N_TGT][3];
    __shared__ int          s_cnt;
    __shared__ int          s_excl[64];   // conf-element offsets within p
    __shared__ int          s_ecnt;

    float local = 0.0f;

    // ---- dense noobj over ALL cells (no target dependency), weight 0.5 ----
    {   // p0: HW=169 (odd) -> scalar
        constexpr int HW = 169;
        for (int i = gtid; i < 96 * HW; i += TTOT) {
            const int plane = i / HW;
            const int pix   = i - plane * HW;
            local += 0.5f * sp(p0[(size_t)(plane * 85 + 4) * HW + pix]);
        }
    }
    local += 0.5f * dense_sum4<676 >(p1, gtid);
    local += 0.5f * dense_sum4<2704>(p2, gtid);

    // ---- blocks 0..95: per-(b,scale) target build + sparse + exclusion correction ----
    if (bid < 96) {
        const int b = bid / 3;
        const int s = bid % 3;
        const int Wd = (s == 0) ? 13 : (s == 1) ? 26 : 52;
        const int HW = Wd * Wd;
        const float* __restrict__ p = (s == 0) ? p0 : (s == 1) ? p1 : p2;

        if (tid == 0) {
            const int abase = (2 - s) * 3;   // masks: s0->{6,7,8}, s1->{3,4,5}, s2->{0,1,2}
            float aw[3], ah[3];
            #pragma unroll
            for (int a = 0; a < 3; a++) {
                aw[a] = anchors[(abase + a) * 2 + 0] * (1.0f / 416.0f);
                ah[a] = anchors[(abase + a) * 2 + 1] * (1.0f / 416.0f);
            }
            int cnt = 0, ecnt = 0;
            for (int n = 0; n < N_TGT; n++) {
                if (valid[b * N_TGT + n] == 0u) continue;
                const float* t = targets + (size_t)(b * N_TGT + n) * 5;
                const float gx = t[0], gy = t[1], gw = t[2], gh = t[3];
                const int gc = (int)t[4];

                const float gxW = gx * (float)Wd;
                const float gyH = gy * (float)Wd;
                const int gi = min((int)gxW, Wd - 1);
                const int gj = min((int)gyH, Wd - 1);

                float best_iou = -1.0f; int best = 0;
                #pragma unroll
                for (int a = 0; a < 3; a++) {
                    const float inter = fminf(gw, aw[a]) * fminf(gh, ah[a]);
                    const float uni   = gw * gh + aw[a] * ah[a] - inter + 1e-16f;
                    const float iou   = inter / uni;
                    if (iou > 0.5f) {
                        const int off = ((b * 3 + a) * 85 + 4) * HW + gj * Wd + gi;
                        int e; for (e = 0; e < ecnt; e++) if (s_excl[e] == off) break;
                        if (e == ecnt) s_excl[ecnt++] = off;
                    }
                    if (iou > best_iou) { best_iou = iou; best = a; }
                }
                {   // positive cell is always excluded from noobj
                    const int off = ((b * 3 + best) * 85 + 4) * HW + gj * Wd + gi;
                    int e; for (e = 0; e < ecnt; e++) if (s_excl[e] == off) break;
                    if (e == ecnt) s_excl[ecnt++] = off;
                }
                // last-write-wins dedup on (best, gj, gi); class bits union (JAX .set scatter)
                const int k = (best << 16) | (gj << 8) | gi;
                int j; for (j = 0; j < cnt; j++) if (s_key[j] == k) break;
                if (j == cnt) {
                    s_key[cnt] = k;
                    s_cls[cnt][0] = s_cls[cnt][1] = s_cls[cnt][2] = 0u;
                    cnt++;
                }
                s_tx[j] = gxW - (float)gi;
                s_ty[j] = gyH - (float)gj;
                s_tw[j] = logf(gw / aw[best]);   // precise log here (few of them)
                s_th[j] = logf(gh / ah[best]);
                s_cls[j][gc >> 5] |= 1u << (gc & 31);
            }
            s_cnt = cnt; s_ecnt = ecnt;
            if (cnt) atomicAdd(&g_numpos, cnt);
        }
        __syncthreads();

        // exclusion correction: subtract 0.5*sp(conf) at excluded cells
        const int ecnt = s_ecnt;
        for (int e = tid; e < ecnt; e += BLOCK)
            local -= 0.5f * sp(p[s_excl[e]]);

        // sparse positive losses: one warp per entry, 85 channels across lanes
        const int warp = tid >> 5, lane = tid & 31;
        const int cnt = s_cnt;
        for (int j = warp; j < cnt; j += 8) {
            const int k  = s_key[j];
            const int a  = k >> 16;
            const int gj = (k >> 8) & 255;
            const int gi = k & 255;
            const float tx = s_tx[j], ty = s_ty[j], tw = s_tw[j], th = s_th[j];
            const unsigned int m0 = s_cls[j][0], m1 = s_cls[j][1], m2 = s_cls[j][2];
            const float* base = p + (size_t)((b * 3 + a) * 85) * HW + gj * Wd + gi;

            float sum = 0.0f;
            for (int c = lane; c < 85; c += 32) {
                const float x = base[(size_t)c * HW];
                float v;
                if (c == 0)      v = 5.0f * (sp(x) - x * tx);
                else if (c == 1) v = 5.0f * (sp(x) - x * ty);
                else if (c == 2) { const float d = x - tw; v = 5.0f * d * d; }
                else if (c == 3) { const float d = x - th; v = 5.0f * d * d; }
                else if (c == 4) v = sp(-x);
                else {
                    const int cc = c - 5;
                    const unsigned int mw = (cc < 32) ? m0 : (cc < 64) ? m1 : m2;
                    const float t = ((mw >> (cc & 31)) & 1u) ? 1.0f : 0.0f;
                    v = sp(x) - x * t;
                }
                sum += v;
            }
            local += sum;   // per-lane partial; block reduction sums it
        }
    }

    // ---- block reduction -> one double atomic per block ----
    #pragma unroll
    for (int off = 16; off; off >>= 1)
        local += __shfl_down_sync(0xffffffffu, local, off);
    __shared__ float wred[BLOCK / 32];
    if ((tid & 31) == 0) wred[tid >> 5] = local;
    __syncthreads();
    if (tid == 0) {
        float tot = 0.0f;
        #pragma unroll
        for (int w = 0; w < BLOCK / 32; w++) tot += wred[w];
        atomicAdd(&g_total, (double)tot);
        __threadfence();
        const unsigned int old = atomicAdd(&g_done, 1u);
        if (old == GRID - 1) {
            // all contributions visible (each block fenced before its g_done add)
            const double T  = atomicAdd(&g_total, 0.0);
            const int    np = atomicAdd(&g_numpos, 0);
            out[0] = (float)((np > 0) ? T / (double)np : T / (double)B_SZ);
            // reset for next graph replay
            g_total  = 0.0;
            g_numpos = 0;
            __threadfence();
            g_done = 0u;
        }
    }
}

extern "C" void kernel_launch(void* const* d_in, const int* in_sizes, int n_in,
                              void* d_out, int out_size)
{
    const float* p0      = (const float*)d_in[0];
    const float* p1      = (const float*)d_in[1];
    const float* p2      = (const float*)d_in[2];
    const float* targets = (const float*)d_in[3];
    const unsigned int* valid = (const unsigned int*)d_in[4];
    const float* anchors = (const float*)d_in[5];

    k_main<<<GRID, BLOCK>>>(p0, p1, p2, targets, valid, anchors, (float*)d_out);
}

// round 16
// speedup vs baseline: 1.3032x; 1.1476x over previous
#include <cuda_runtime.h>

// YOLOv3 loss — single fused kernel, parallel target build.
// Identity: sum_{noobj} sp(conf) = sum_{ALL cells} sp(conf) - sum_{excluded} sp(conf).
// Blocks 0..95: per-(b,scale) target build (lanes 0..19 parallel) + smem dedup (tid0)
//               + sparse positive losses + exclusion corrections.
// Blocks 96..383: dense conf-channel softplus sum only.
// Device-global accumulators reset by the finalizing block => graph-replay safe.

#define N_TGT 20
#define B_SZ 32
#define GRID 384
#define NDENSE (GRID - 96)          // 288 dense blocks
#define BLOCK 256
#define DTOT (NDENSE * BLOCK)

__device__ double       g_total  = 0.0;
__device__ int          g_numpos = 0;
__device__ unsigned int g_done   = 0u;

// fast softplus: max(x,0) + log(1 + exp(-|x|)) via raw MUFU ex2/lg2. abs err < 1.2e-7/term.
__device__ __forceinline__ float sp(float x) {
    const float t = __expf(-fabsf(x));
    return fmaxf(x, 0.0f) + __logf(1.0f + t);
}

// dense conf-channel softplus sum, float4 (HW divisible by 4); plane = b*3+a, base = plane*85+4
template <int HW>
__device__ __forceinline__ float dense_sum4(const float* __restrict__ p, int gtid) {
    constexpr int Q = HW / 4;
    float s = 0.0f;
    for (int i = gtid; i < 96 * Q; i += DTOT) {
        const int plane = i / Q;
        const int q     = i - plane * Q;
        const float4 v = *(const float4*)(p + (size_t)(plane * 85 + 4) * HW + 4 * q);
        s += sp(v.x) + sp(v.y) + sp(v.z) + sp(v.w);
    }
    return s;
}

__global__ __launch_bounds__(BLOCK)
void k_main(const float* __restrict__ p0,
            const float* __restrict__ p1,
            const float* __restrict__ p2,
            const float* __restrict__ targets,
            const unsigned int* __restrict__ valid,   // [B,N] nonzero = valid
            const float* __restrict__ anchors,        // [9,2]
            float* __restrict__ out)
{
    const int tid = threadIdx.x;
    const int bid = blockIdx.x;

    float local = 0.0f;

    if (bid >= 96) {
        // ================= dense blocks =================
        const int gtid = (bid - 96) * BLOCK + tid;
        {   // p0: HW=169 (odd) -> scalar
            constexpr int HW = 169;
            for (int i = gtid; i < 96 * HW; i += DTOT) {
                const int plane = i / HW;
                const int pix   = i - plane * HW;
                local += 0.5f * sp(p0[(size_t)(plane * 85 + 4) * HW + pix]);
            }
        }
        local += 0.5f * dense_sum4<676 >(p1, gtid);
        local += 0.5f * dense_sum4<2704>(p2, gtid);
    } else {
        // ================= special blocks: one per (b,scale) =================
        const int b = bid / 3;
        const int s = bid % 3;
        const int Wd = (s == 0) ? 13 : (s == 1) ? 26 : 52;
        const int HW = Wd * Wd;
        const float* __restrict__ p = (s == 0) ? p0 : (s == 1) ? p1 : p2;

        // per-target parallel results (lanes 0..19)
        __shared__ int   t_key[N_TGT];    // -1 invalid; else (best<<16)|(gj<<8)|gi
        __shared__ int   t_ign[N_TGT];    // 3 ignore bits (anchor a -> bit a)
        __shared__ float t_tx[N_TGT], t_ty[N_TGT], t_tw[N_TGT], t_th[N_TGT];
        __shared__ int   t_cls[N_TGT];
        // deduped outputs
        __shared__ int          s_key[N_TGT];
        __shared__ float        s_tx[N_TGT], s_ty[N_TGT], s_tw[N_TGT], s_th[N_TGT];
        __shared__ unsigned int s_cls[N_TGT][3];
        __shared__ int          s_cnt;
        __shared__ int          s_excl[80];   // conf-element offsets (deduped)
        __shared__ int          s_ecnt;

        // ---- phase 1: parallel per-target processing (all global loads up front) ----
        if (tid < N_TGT) {
            const int n = tid;
            // Independent scalar loads: valid bit + 5 target floats issue concurrently
            // (targets is always fully populated, so loading before the valid check is
            // safe; scalar LDGs avoid the 8B-alignment trap of float2 at stride-5 bases)
            const unsigned int v = valid[b * N_TGT + n];
            const float* t = targets + (size_t)(b * N_TGT + n) * 5;
            const float gx = t[0], gy = t[1], gw = t[2], gh = t[3], t4 = t[4];

            int key = -1, ign = 0, gc = 0;
            float vtx = 0.f, vty = 0.f, vtw = 0.f, vth = 0.f;
            if (v) {
                gc = (int)t4;
                const int abase = (2 - s) * 3;   // s0->{6,7,8}, s1->{3,4,5}, s2->{0,1,2}
                const float gxW = gx * (float)Wd;
                const float gyH = gy * (float)Wd;
                const int gi = min((int)gxW, Wd - 1);
                const int gj = min((int)gyH, Wd - 1);
                float best_iou = -1.0f; int best = 0;
                #pragma unroll
                for (int a = 0; a < 3; a++) {
                    const float aw = anchors[(abase + a) * 2 + 0] * (1.0f / 416.0f);
                    const float ah = anchors[(abase + a) * 2 + 1] * (1.0f / 416.0f);
                    const float inter = fminf(gw, aw) * fminf(gh, ah);
                    const float uni   = gw * gh + aw * ah - inter + 1e-16f;
                    const float iou   = inter / uni;
                    if (iou > 0.5f) ign |= (1 << a);
                    if (iou > best_iou) { best_iou = iou; best = a; }
                }
                const float awb = anchors[(abase + best) * 2 + 0] * (1.0f / 416.0f);
                const float ahb = anchors[(abase + best) * 2 + 1] * (1.0f / 416.0f);
                vtx = gxW - (float)gi;
                vty = gyH - (float)gj;
                vtw = logf(gw / awb);
                vth = logf(gh / ahb);
                key = (best << 16) | (gj << 8) | gi;
            }
            t_key[n] = key; t_ign[n] = ign; t_cls[n] = gc;
            t_tx[n] = vtx; t_ty[n] = vty; t_tw[n] = vtw; t_th[n] = vth;
        }
        __syncthreads();

        // ---- phase 2: order-dependent dedup, pure smem/ALU on tid 0 ----
        if (tid == 0) {
            int cnt = 0, ecnt = 0;
            for (int n = 0; n < N_TGT; n++) {
                const int key = t_key[n];
                if (key < 0) continue;
                const int best = key >> 16;
                const int gj   = (key >> 8) & 255;
                const int gi   = key & 255;
                const int ign  = t_ign[n];
                const int cellbase = (b * 3) * 85 * HW + 4 * HW + gj * Wd + gi;
                #pragma unroll
                for (int a = 0; a < 3; a++) {
                    if ((ign >> a) & 1) {
                        const int off = cellbase + a * 85 * HW;
                        int e; for (e = 0; e < ecnt; e++) if (s_excl[e] == off) break;
                        if (e == ecnt) s_excl[ecnt++] = off;
                    }
                }
                {   // positive cell always excluded from noobj
                    const int off = cellbase + best * 85 * HW;
                    int e; for (e = 0; e < ecnt; e++) if (s_excl[e] == off) break;
                    if (e == ecnt) s_excl[ecnt++] = off;
                }
                // last-write-wins dedup; class bits union (JAX .set scatter semantics)
                int j; for (j = 0; j < cnt; j++) if (s_key[j] == key) break;
                if (j == cnt) {
                    s_key[cnt] = key;
                    s_cls[cnt][0] = s_cls[cnt][1] = s_cls[cnt][2] = 0u;
                    cnt++;
                }
                s_tx[j] = t_tx[n]; s_ty[j] = t_ty[n];
                s_tw[j] = t_tw[n]; s_th[j] = t_th[n];
                const int gc = t_cls[n];
                s_cls[j][gc >> 5] |= 1u << (gc & 31);
            }
            s_cnt = cnt; s_ecnt = ecnt;
            if (cnt) atomicAdd(&g_numpos, cnt);
        }
        __syncthreads();

        // ---- phase 3: exclusion corrections (subtract 0.5*sp at excluded conf cells) ----
        const int ecnt = s_ecnt;
        for (int e = tid; e < ecnt; e += BLOCK)
            local -= 0.5f * sp(p[s_excl[e]]);

        // ---- phase 4: sparse positive losses: one warp per entry, 85 chans across lanes ----
        const int warp = tid >> 5, lane = tid & 31;
        const int cnt = s_cnt;
        for (int j = warp; j < cnt; j += BLOCK / 32) {
            const int k  = s_key[j];
            const int a  = k >> 16;
            const int gj = (k >> 8) & 255;
            const int gi = k & 255;
            const float tx = s_tx[j], ty = s_ty[j], tw = s_tw[j], th = s_th[j];
            const unsigned int m0 = s_cls[j][0], m1 = s_cls[j][1], m2 = s_cls[j][2];
            const float* base = p + (size_t)((b * 3 + a) * 85) * HW + gj * Wd + gi;

            float sum = 0.0f;
            for (int c = lane; c < 85; c += 32) {
                const float x = base[(size_t)c * HW];
                float v;
                if (c == 0)      v = 5.0f * (sp(x) - x * tx);
                else if (c == 1) v = 5.0f * (sp(x) - x * ty);
                else if (c == 2) { const float d = x - tw; v = 5.0f * d * d; }
                else if (c == 3) { const float d = x - th; v = 5.0f * d * d; }
                else if (c == 4) v = sp(-x);
                else {
                    const int cc = c - 5;
                    const unsigned int mw = (cc < 32) ? m0 : (cc < 64) ? m1 : m2;
                    const float t = ((mw >> (cc & 31)) & 1u) ? 1.0f : 0.0f;
                    v = sp(x) - x * t;
                }
                sum += v;
            }
            local += sum;   // per-lane partial; block reduction sums it
        }
    }

    // ---- block reduction -> one double atomic per block ----
    #pragma unroll
    for (int off = 16; off; off >>= 1)
        local += __shfl_down_sync(0xffffffffu, local, off);
    __shared__ float wred[BLOCK / 32];
    if ((tid & 31) == 0) wred[tid >> 5] = local;
    __syncthreads();
    if (tid == 0) {
        float tot = 0.0f;
        #pragma unroll
        for (int w = 0; w < BLOCK / 32; w++) tot += wred[w];
        atomicAdd(&g_total, (double)tot);
        __threadfence();
        const unsigned int old = atomicAdd(&g_done, 1u);
        if (old == GRID - 1) {
            const double T  = atomicAdd(&g_total, 0.0);
            const int    np = atomicAdd(&g_numpos, 0);
            out[0] = (float)((np > 0) ? T / (double)np : T / (double)B_SZ);
            // reset for next graph replay
            g_total  = 0.0;
            g_numpos = 0;
            __threadfence();
            g_done = 0u;
        }
    }
}

extern "C" void kernel_launch(void* const* d_in, const int* in_sizes, int n_in,
                              void* d_out, int out_size)
{
    const float* p0      = (const float*)d_in[0];
    const float* p1      = (const float*)d_in[1];
    const float* p2      = (const float*)d_in[2];
    const float* targets = (const float*)d_in[3];
    const unsigned int* valid = (const unsigned int*)d_in[4];
    const float* anchors = (const float*)d_in[5];

    k_main<<<GRID, BLOCK>>>(p0, p1, p2, targets, valid, anchors, (float*)d_out);
}